// round 2
// baseline (speedup 1.0000x reference)
#include <cuda_runtime.h>
#include <math.h>

#define NB 2
#define MB 16384
#define PB 5023
#define KB 4
#define CB 32
#define HPX 256
#define REG 129
#define ROFF 127
#define NQ (NB*MB)

#define DENS_OFF 0
#define RGB_OFF  (NQ)
#define DIST_OFF (NQ + NQ*32)

// ---------------- device scratch ----------------
__device__ __align__(16) float4 g_pts4[NB*PB];
__device__ __align__(16) float  g_texT[NB*3*REG*REG*CB];
__device__ __align__(16) float  g_knn_d[NQ*KB];
__device__ int    g_knn_i[NQ*KB];
__device__ float  g_wsum[NB*KB];
__device__ __align__(16) float  g_feat[NQ*64];
__device__ __align__(16) float  g_h1[NQ*128];
__device__ __align__(16) float  g_h2[NQ*128];
__device__ __align__(16) float  g_h3[NQ*128];
__device__ __align__(16) float  g_hr[NQ*64];

// ---------------- helpers ----------------
__device__ __forceinline__ unsigned f2ord(float f){
    unsigned b = __float_as_uint(f);
    return (b & 0x80000000u) ? ~b : (b | 0x80000000u);
}
__device__ __forceinline__ float ord2f(unsigned u){
    unsigned b = (u & 0x80000000u) ? (u & 0x7fffffffu) : ~u;
    return __uint_as_float(b);
}
__device__ __forceinline__ unsigned long long umin64(unsigned long long a, unsigned long long b){ return a<b?a:b; }
__device__ __forceinline__ unsigned long long umax64(unsigned long long a, unsigned long long b){ return a>b?a:b; }

// keep 4 smallest, sorted k0<=k1<=k2<=k3; requires c <= k3
__device__ __forceinline__ void insert4(unsigned long long& k0, unsigned long long& k1,
                                        unsigned long long& k2, unsigned long long& k3,
                                        unsigned long long c){
    unsigned long long mn2 = umin64(k2,c), mn1 = umin64(k1,c), mn0 = umin64(k0,c);
    k3 = umax64(k2,c);
    k2 = umax64(k1,mn2);
    k1 = umax64(k0,mn1);
    k0 = mn0;
}

// ---------------- K1: pack points ----------------
__global__ void k_prep(const float* __restrict__ ppos){
    int i = blockIdx.x*blockDim.x + threadIdx.x;
    if (i < NB*PB){
        float x = ppos[3*i+0], y = ppos[3*i+1], z = ppos[3*i+2];
        g_pts4[i] = make_float4(x,y,z, x*x+y*y+z*z);
    }
}

// ---------------- K2: transpose accessed triplane region to [y,x,c] ----------------
__global__ void k_transpose(const float* __restrict__ tpl){
    __shared__ float tile[32][33];
    int z  = blockIdx.z;      // n*3+pl
    int ry = blockIdx.y;      // 0..128
    int xt = blockIdx.x*32;
    int tx = threadIdx.x, ty = threadIdx.y;
    int gx = xt + tx;
    if (gx < REG)
        tile[ty][tx] = tpl[(z*CB + ty)*(HPX*HPX) + (ROFF+ry)*HPX + (ROFF+gx)];
    __syncthreads();
    int xo = xt + ty;
    if (xo < REG)
        g_texT[((z*REG + ry)*REG + xo)*CB + tx] = tile[tx][ty];
}

// ---------------- K3: exact KNN (K=4), lane=query, warp=P-chunk ----------------
__global__ __launch_bounds__(128) void k_knn(const float* __restrict__ coords,
                                             float* __restrict__ out){
    const int CH = (PB + 3) / 4;
    int q0 = blockIdx.x * 32;
    int lane = threadIdx.x & 31, wz = threadIdx.x >> 5;
    int q = q0 + lane;
    int n = q / MB;
    const float4* pts = g_pts4 + n*PB;

    float cx = coords[3*q+0], cy = coords[3*q+1], cz = coords[3*q+2];
    float cc  = cx*cx + cy*cy + cz*cz;
    float ncx = -2.f*cx, ncy = -2.f*cy, ncz = -2.f*cz;

    unsigned long long k0=~0ull,k1=~0ull,k2=~0ull,k3=~0ull;
    int js = wz*CH, je = min(PB, js+CH);
    #pragma unroll 4
    for (int j = js; j < je; ++j){
        float4 p = __ldg(&pts[j]);
        float t = cc + p.w;
        t = fmaf(p.x, ncx, t);
        t = fmaf(p.y, ncy, t);
        t = fmaf(p.z, ncz, t);
        unsigned long long key = ((unsigned long long)f2ord(t) << 32) | (unsigned)j;
        bool ins = key < k3;
        if (__any_sync(0xffffffffu, ins)){
            unsigned long long c = ins ? key : k3;
            insert4(k0,k1,k2,k3,c);
        }
    }

    __shared__ unsigned long long sk[4][32][4];
    sk[wz][lane][0]=k0; sk[wz][lane][1]=k1; sk[wz][lane][2]=k2; sk[wz][lane][3]=k3;
    __syncthreads();

    if (threadIdx.x < 32){
        int qq = q0 + threadIdx.x;
        unsigned long long r0=~0ull,r1=~0ull,r2=~0ull,r3=~0ull;
        #pragma unroll
        for (int z=0; z<4; ++z)
            #pragma unroll
            for (int s=0; s<4; ++s){
                unsigned long long c = sk[z][threadIdx.x][s];
                if (c < r3) insert4(r0,r1,r2,r3,c);
            }
        unsigned long long rr[4] = {r0,r1,r2,r3};
        #pragma unroll
        for (int r=0; r<4; ++r){
            float d  = ord2f((unsigned)(rr[r] >> 32));
            int idx  = (int)(unsigned)rr[r];
            g_knn_d[qq*4+r]  = d;
            g_knn_i[qq*4+r]  = idx;
            out[DIST_OFF + qq*4+r] = d;
        }
    }
}

// ---------------- K4: S[n,k] = sum_m 1/dist ----------------
__global__ void k_wsum(){
    int nk = blockIdx.x;
    int n = nk / KB, k = nk % KB;
    float acc = 0.f;
    for (int m = threadIdx.x; m < MB; m += 256)
        acc += 1.0f / g_knn_d[(n*MB + m)*KB + k];
    __shared__ float sb[256];
    sb[threadIdx.x] = acc;
    __syncthreads();
    for (int s=128; s>0; s>>=1){
        if (threadIdx.x < s) sb[threadIdx.x] += sb[threadIdx.x+s];
        __syncthreads();
    }
    if (threadIdx.x == 0) g_wsum[nk] = sb[0];
}

// ---------------- K5: triplane sampling (warp=query, lane=channel) ----------------
__global__ __launch_bounds__(256) void k_tex(const float* __restrict__ coords){
    int q = blockIdx.x*8 + (threadIdx.x >> 5);
    int lane = threadIdx.x & 31;
    int n = q / MB;
    float c0 = __ldg(&coords[3*q+0]);
    float c1 = __ldg(&coords[3*q+1]);
    float c2 = __ldg(&coords[3*q+2]);
    float gxs[3] = {c0, c0, c2};
    float gys[3] = {c1, c2, c0};
    float acc = 0.f;
    #pragma unroll
    for (int pl=0; pl<3; ++pl){
        float x = (gxs[pl]+1.f)*(HPX*0.5f) - 0.5f;
        float y = (gys[pl]+1.f)*(HPX*0.5f) - 0.5f;
        float fx0 = floorf(x), fy0 = floorf(y);
        int ix0 = (int)fx0, iy0 = (int)fy0;
        float wx1 = x - fx0, wx0 = 1.f - wx1;
        float wy1 = y - fy0, wy0 = 1.f - wy1;
        const float* base = g_texT + (size_t)(n*3 + pl)*REG*REG*CB;
        #pragma unroll
        for (int dy=0; dy<2; ++dy)
            #pragma unroll
            for (int dx=0; dx<2; ++dx){
                int ix = ix0 + dx, iy = iy0 + dy;
                bool v = (ix>=0) & (ix<HPX) & (iy>=0) & (iy<HPX);
                int rx = min(max(ix-ROFF,0), REG-1);
                int ry = min(max(iy-ROFF,0), REG-1);
                float w = (dx?wx1:wx0) * (dy?wy1:wy0) * (v?1.f:0.f);
                acc = fmaf(w, base[(ry*REG + rx)*CB + lane], acc);
            }
    }
    g_feat[q*64 + lane] = acc * (1.f/3.f);
}

// ---------------- K6: per-neighbor MLP + weighted sum (warp=query) ----------------
__global__ __launch_bounds__(256) void k_pmlp(const float* __restrict__ coords,
                                              const float* __restrict__ emb,
                                              const float* __restrict__ pw1, const float* __restrict__ pb1,
                                              const float* __restrict__ pw2, const float* __restrict__ pb2){
    __shared__ __align__(16) float s_w1[59*64];
    __shared__ __align__(8)  float s_b1[64];
    __shared__ __align__(16) float s_w2[64*32];
    __shared__ float s_b2[32];
    __shared__ float s_in[8][60];
    __shared__ float s_h [8][64];

    for (int i = threadIdx.x; i < 59*64; i += 256) s_w1[i] = pw1[i];
    for (int i = threadIdx.x; i < 64;    i += 256) s_b1[i] = pb1[i];
    for (int i = threadIdx.x; i < 64*32; i += 256) s_w2[i] = pw2[i];
    for (int i = threadIdx.x; i < 32;    i += 256) s_b2[i] = pb2[i];
    __syncthreads();

    int w = threadIdx.x >> 5, lane = threadIdx.x & 31;
    int q = blockIdx.x*8 + w;
    int n = q / MB;
    float cx = __ldg(&coords[3*q+0]);
    float cy = __ldg(&coords[3*q+1]);
    float cz = __ldg(&coords[3*q+2]);
    float invS[4];
    #pragma unroll
    for (int k=0;k<4;++k) invS[k] = 1.0f / g_wsum[n*KB + k];

    float pts = 0.f;
    #pragma unroll 1
    for (int k=0; k<4; ++k){
        int   idx  = g_knn_i[q*4+k];
        float dist = g_knn_d[q*4+k];
        float4 p = __ldg(&g_pts4[n*PB + idx]);
        float rx = cx - p.x, ry = cy - p.y, rz = cz - p.z;
        float L = sqrtf(rx*rx + ry*ry + rz*rz);
        L = fmaxf(L, 1e-12f);
        rx /= L; ry /= L; rz /= L;

        s_in[w][lane] = emb[idx*32 + lane];
        if (lane < 12){
            float comp = (lane<4)?rx:((lane<8)?ry:rz);
            s_in[w][32+lane] = sinf(comp * (float)(1<<(lane&3)));
        } else if (lane < 24){
            int l = lane-12;
            float comp = (l<4)?rx:((l<8)?ry:rz);
            s_in[w][32+lane] = cosf(comp * (float)(l<4 ? (1<<l) : (1<<(l&3))));
        } else if (lane < 27){
            s_in[w][32+lane] = (lane==24)?rx:((lane==25)?ry:rz);
        }
        __syncwarp();

        float a0 = s_b1[2*lane], a1 = s_b1[2*lane+1];
        #pragma unroll 4
        for (int i=0;i<59;++i){
            float ai = s_in[w][i];
            float2 wv = *(const float2*)&s_w1[i*64 + 2*lane];
            a0 = fmaf(ai, wv.x, a0);
            a1 = fmaf(ai, wv.y, a1);
        }
        s_h[w][2*lane]   = fmaxf(a0, 0.f);
        s_h[w][2*lane+1] = fmaxf(a1, 0.f);
        __syncwarp();

        float acc = s_b2[lane];
        #pragma unroll 8
        for (int i=0;i<64;++i)
            acc = fmaf(s_h[w][i], s_w2[i*32 + lane], acc);

        float wk = (1.0f/dist) * invS[k];
        pts = fmaf(acc, wk, pts);
        __syncwarp();
    }
    g_feat[q*64 + 32 + lane] = pts;
}

// ---------------- K7: generic dense layer [NQ,I] @ [I,O] + b ----------------
template<int I, int O, bool RELU>
__global__ __launch_bounds__(256) void k_dense(const float* __restrict__ A,
                                               const float* __restrict__ W,
                                               const float* __restrict__ Bv,
                                               float* __restrict__ Out){
    __shared__ float s_act[64*33];
    __shared__ __align__(16) float s_w[32*O];
    __shared__ __align__(8)  float s_b[O];
    const int t = threadIdx.x;
    for (int i=t;i<O;i+=256) s_b[i]=Bv[i];
    int qg = t >> 3;        // 0..31 -> queries qg, qg+32
    int part = t & 7;
    int qb = blockIdx.x * 64;

    float2 acc0[O/16], acc1[O/16];
    #pragma unroll
    for (int j=0;j<O/16;++j){ acc0[j]=make_float2(0.f,0.f); acc1[j]=make_float2(0.f,0.f); }

    for (int kc=0;kc<I/32;++kc){
        __syncthreads();
        for (int x=t;x<64*32;x+=256){
            int q=x>>5, ii=x&31;
            s_act[q*33+ii]=A[(qb+q)*I + kc*32+ii];
        }
        for (int x=t;x<32*O;x+=256) s_w[x]=W[kc*32*O + x];
        __syncthreads();
        #pragma unroll 4
        for (int ii=0;ii<32;++ii){
            float a0=s_act[qg*33+ii], a1=s_act[(qg+32)*33+ii];
            #pragma unroll
            for (int j=0;j<O/16;++j){
                float2 wv=*(const float2*)&s_w[ii*O + j*16 + 2*part];
                acc0[j].x = fmaf(a0,wv.x,acc0[j].x); acc0[j].y = fmaf(a0,wv.y,acc0[j].y);
                acc1[j].x = fmaf(a1,wv.x,acc1[j].x); acc1[j].y = fmaf(a1,wv.y,acc1[j].y);
            }
        }
    }
    #pragma unroll
    for (int j=0;j<O/16;++j){
        int o=j*16+2*part;
        float2 b=*(const float2*)&s_b[o];
        float2 v0=make_float2(acc0[j].x+b.x, acc0[j].y+b.y);
        float2 v1=make_float2(acc1[j].x+b.x, acc1[j].y+b.y);
        if (RELU){
            v0.x=fmaxf(v0.x,0.f); v0.y=fmaxf(v0.y,0.f);
            v1.x=fmaxf(v1.x,0.f); v1.y=fmaxf(v1.y,0.f);
        }
        *(float2*)&Out[(size_t)(qb+qg)*O+o]=v0;
        *(float2*)&Out[(size_t)(qb+qg+32)*O+o]=v1;
    }
}

// ---------------- K8: density head + rgb layer 1 ----------------
__global__ __launch_bounds__(256) void k_headA(const float* __restrict__ coords,
                                               const float* __restrict__ dirs,
                                               const float* __restrict__ dw, const float* __restrict__ db,
                                               const float* __restrict__ rw1, const float* __restrict__ rb1,
                                               float* __restrict__ out){
    __shared__ __align__(16) float s_w[155*64];
    __shared__ __align__(8)  float s_b1[64];
    __shared__ float s_in[8][156];

    for (int i=threadIdx.x;i<155*64;i+=256) s_w[i]=rw1[i];
    for (int i=threadIdx.x;i<64;i+=256) s_b1[i]=rb1[i];
    __syncthreads();

    int w = threadIdx.x >> 5, lane = threadIdx.x & 31;
    int q = blockIdx.x*8 + w;

    float4 f4 = *(const float4*)&g_h3[(size_t)q*128 + lane*4];
    s_in[w][lane*4+0]=f4.x; s_in[w][lane*4+1]=f4.y;
    s_in[w][lane*4+2]=f4.z; s_in[w][lane*4+3]=f4.w;

    float dx=__ldg(&dirs[3*q+0]), dy=__ldg(&dirs[3*q+1]), dz=__ldg(&dirs[3*q+2]);
    float L=sqrtf(dx*dx+dy*dy+dz*dz); L=fmaxf(L,1e-12f);
    dx/=L; dy/=L; dz/=L;
    if (lane < 12){
        float comp=(lane<4)?dx:((lane<8)?dy:dz);
        s_in[w][128+lane]=sinf(comp*(float)(1<<(lane&3)));
    } else if (lane < 24){
        int l=lane-12;
        float comp=(l<4)?dx:((l<8)?dy:dz);
        s_in[w][128+lane]=cosf(comp*(float)(1<<(l&3)));
    } else if (lane < 27){
        s_in[w][128+lane]=(lane==24)?dx:((lane==25)?dy:dz);
    }
    __syncwarp();

    // density
    float part=0.f;
    #pragma unroll
    for (int r=0;r<4;++r){
        int i=lane*4+r;
        part = fmaf(s_in[w][i], __ldg(&dw[i]), part);
    }
    #pragma unroll
    for (int s=16;s>0;s>>=1) part += __shfl_xor_sync(0xffffffffu, part, s);
    if (lane==0){
        float u = part + __ldg(&db[0]);
        float x = 10.f*u;
        float sp = (x > 20.f) ? x : log1pf(expf(x));
        float c0=__ldg(&coords[3*q+0]), c1=__ldg(&coords[3*q+1]), c2=__ldg(&coords[3*q+2]);
        bool sel = (c0>-1.f)&&(c0<1.f)&&(c1>-1.f)&&(c1<1.f)&&(c2>-1.f)&&(c2<1.f);
        float raw = (sp*0.1f) * (sel?1.f:0.f);
        out[DENS_OFF + q] = 1.f - expf(-raw);
    }

    float a0=s_b1[2*lane], a1=s_b1[2*lane+1];
    #pragma unroll 5
    for (int i=0;i<155;++i){
        float ai=s_in[w][i];
        float2 wv=*(const float2*)&s_w[i*64 + 2*lane];
        a0=fmaf(ai,wv.x,a0); a1=fmaf(ai,wv.y,a1);
    }
    float2 hv = make_float2(fmaxf(a0,0.f), fmaxf(a1,0.f));
    *(float2*)&g_hr[(size_t)q*64 + 2*lane] = hv;
}

// ---------------- K9: rgb layer 2 + sigmoid ----------------
__global__ __launch_bounds__(256) void k_headB(const float* __restrict__ rw2,
                                               const float* __restrict__ rb2,
                                               float* __restrict__ out){
    __shared__ __align__(16) float s_w2[64*32];
    __shared__ float s_b2[32];
    __shared__ float s_h[8][64];
    for (int i=threadIdx.x;i<64*32;i+=256) s_w2[i]=rw2[i];
    for (int i=threadIdx.x;i<32;i+=256) s_b2[i]=rb2[i];
    __syncthreads();

    int w=threadIdx.x>>5, lane=threadIdx.x&31;
    int q=blockIdx.x*8 + w;
    s_h[w][lane]    = g_hr[(size_t)q*64 + lane];
    s_h[w][32+lane] = g_hr[(size_t)q*64 + 32 + lane];
    __syncwarp();

    float acc = s_b2[lane];
    #pragma unroll 8
    for (int i=0;i<64;++i)
        acc = fmaf(s_h[w][i], s_w2[i*32+lane], acc);
    if (lane < 3)
        acc = 1.f/(1.f+expf(-acc)) * 1.002f - 0.001f;
    out[RGB_OFF + (size_t)q*32 + lane] = acc;
}

// ---------------- launcher ----------------
extern "C" void kernel_launch(void* const* d_in, const int* in_sizes, int n_in,
                              void* d_out, int out_size) {
    const float* coords = (const float*)d_in[0];
    const float* dirs   = (const float*)d_in[1];
    const float* ppos   = (const float*)d_in[2];
    const float* tpl    = (const float*)d_in[3];
    const float* emb    = (const float*)d_in[4];
    const float* pw1    = (const float*)d_in[5];
    const float* pb1    = (const float*)d_in[6];
    const float* pw2    = (const float*)d_in[7];
    const float* pb2    = (const float*)d_in[8];
    const float* fw1    = (const float*)d_in[9];
    const float* fb1    = (const float*)d_in[10];
    const float* fw2    = (const float*)d_in[11];
    const float* fb2    = (const float*)d_in[12];
    const float* fw3    = (const float*)d_in[13];
    const float* fb3    = (const float*)d_in[14];
    const float* dw     = (const float*)d_in[15];
    const float* db     = (const float*)d_in[16];
    const float* rw1    = (const float*)d_in[17];
    const float* rb1    = (const float*)d_in[18];
    const float* rw2    = (const float*)d_in[19];
    const float* rb2    = (const float*)d_in[20];
    float* out = (float*)d_out;

    float* d_h1; float* d_h2; float* d_h3; float* d_feat;
    cudaGetSymbolAddress((void**)&d_feat, g_feat);
    cudaGetSymbolAddress((void**)&d_h1, g_h1);
    cudaGetSymbolAddress((void**)&d_h2, g_h2);
    cudaGetSymbolAddress((void**)&d_h3, g_h3);

    k_prep<<<(NB*PB+255)/256, 256>>>(ppos);
    k_transpose<<<dim3(5,129,6), dim3(32,32)>>>(tpl);
    k_knn<<<NQ/32, 128>>>(coords, out);
    k_wsum<<<NB*KB, 256>>>();
    k_tex<<<NQ/8, 256>>>(coords);
    k_pmlp<<<NQ/8, 256>>>(coords, emb, pw1, pb1, pw2, pb2);
    k_dense<64,128,true><<<NQ/64, 256>>>(d_feat, fw1, fb1, d_h1);
    k_dense<128,128,true><<<NQ/64, 256>>>(d_h1, fw2, fb2, d_h2);
    k_dense<128,128,false><<<NQ/64, 256>>>(d_h2, fw3, fb3, d_h3);
    k_headA<<<NQ/8, 256>>>(coords, dirs, dw, db, rw1, rb1, out);
    k_headB<<<NQ/8, 256>>>(rw2, rb2, out);
}

// round 3
// speedup vs baseline: 1.0079x; 1.0079x over previous
#include <cuda_runtime.h>
#include <math.h>

#define NB 2
#define MB 16384
#define PB 5023
#define KB 4
#define CB 32
#define HPX 256
#define REG 129
#define ROFF 127
#define NQ (NB*MB)

#define DENS_OFF 0
#define RGB_OFF  (NQ)
#define DIST_OFF (NQ + NQ*32)

// ---------------- device scratch ----------------
__device__ __align__(16) float4 g_pts4[NB*PB];
__device__ __align__(16) float  g_texT[NB*3*REG*REG*CB];
__device__ __align__(16) float  g_knn_d[NQ*KB];
__device__ int    g_knn_i[NQ*KB];
__device__ float  g_wsum[NB*KB];
__device__ __align__(16) float  g_feat[NQ*64];
__device__ __align__(16) float  g_h1[NQ*128];
__device__ __align__(16) float  g_h2[NQ*128];
__device__ __align__(16) float  g_h3[NQ*128];
__device__ __align__(16) float  g_hr[NQ*64];

// ---------------- helpers ----------------
__device__ __forceinline__ unsigned f2ord(float f){
    unsigned b = __float_as_uint(f);
    return (b & 0x80000000u) ? ~b : (b | 0x80000000u);
}
__device__ __forceinline__ float ord2f(unsigned u){
    unsigned b = (u & 0x80000000u) ? (u & 0x7fffffffu) : ~u;
    return __uint_as_float(b);
}
__device__ __forceinline__ unsigned long long umin64(unsigned long long a, unsigned long long b){ return a<b?a:b; }
__device__ __forceinline__ unsigned long long umax64(unsigned long long a, unsigned long long b){ return a>b?a:b; }

// keep 4 smallest, sorted k0<=k1<=k2<=k3; requires c <= k3
__device__ __forceinline__ void insert4(unsigned long long& k0, unsigned long long& k1,
                                        unsigned long long& k2, unsigned long long& k3,
                                        unsigned long long c){
    unsigned long long mn2 = umin64(k2,c), mn1 = umin64(k1,c), mn0 = umin64(k0,c);
    k3 = umax64(k2,c);
    k2 = umax64(k1,mn2);
    k1 = umax64(k0,mn1);
    k0 = mn0;
}

// ---------------- K1: pack points ----------------
__global__ void k_prep(const float* __restrict__ ppos){
    int i = blockIdx.x*blockDim.x + threadIdx.x;
    if (i < NB*PB){
        float x = ppos[3*i+0], y = ppos[3*i+1], z = ppos[3*i+2];
        g_pts4[i] = make_float4(x,y,z, x*x+y*y+z*z);
    }
}

// ---------------- K2: transpose accessed triplane region to [y,x,c] ----------------
__global__ void k_transpose(const float* __restrict__ tpl){
    __shared__ float tile[32][33];
    int z  = blockIdx.z;      // n*3+pl
    int ry = blockIdx.y;      // 0..128
    int xt = blockIdx.x*32;
    int tx = threadIdx.x, ty = threadIdx.y;
    int gx = xt + tx;
    if (gx < REG)
        tile[ty][tx] = tpl[(z*CB + ty)*(HPX*HPX) + (ROFF+ry)*HPX + (ROFF+gx)];
    __syncthreads();
    int xo = xt + ty;
    if (xo < REG)
        g_texT[((z*REG + ry)*REG + xo)*CB + tx] = tile[tx][ty];
}

// ---------------- K3: exact KNN (K=4), lane=query, warp=P-chunk ----------------
__global__ __launch_bounds__(128) void k_knn(const float* __restrict__ coords,
                                             float* __restrict__ out){
    const int CH = (PB + 3) / 4;
    int q0 = blockIdx.x * 32;
    int lane = threadIdx.x & 31, wz = threadIdx.x >> 5;
    int q = q0 + lane;
    int n = q / MB;
    const float4* pts = g_pts4 + n*PB;

    float cx = coords[3*q+0], cy = coords[3*q+1], cz = coords[3*q+2];
    float cc  = cx*cx + cy*cy + cz*cz;
    float ncx = -2.f*cx, ncy = -2.f*cy, ncz = -2.f*cz;

    unsigned long long k0=~0ull,k1=~0ull,k2=~0ull,k3=~0ull;
    int js = wz*CH, je = min(PB, js+CH);
    #pragma unroll 4
    for (int j = js; j < je; ++j){
        float4 p = __ldg(&pts[j]);
        float t = cc + p.w;
        t = fmaf(p.x, ncx, t);
        t = fmaf(p.y, ncy, t);
        t = fmaf(p.z, ncz, t);
        unsigned long long key = ((unsigned long long)f2ord(t) << 32) | (unsigned)j;
        bool ins = key < k3;
        if (__any_sync(0xffffffffu, ins)){
            unsigned long long c = ins ? key : k3;
            insert4(k0,k1,k2,k3,c);
        }
    }

    __shared__ unsigned long long sk[4][32][4];
    sk[wz][lane][0]=k0; sk[wz][lane][1]=k1; sk[wz][lane][2]=k2; sk[wz][lane][3]=k3;
    __syncthreads();

    if (threadIdx.x < 32){
        int qq = q0 + threadIdx.x;
        unsigned long long r0=~0ull,r1=~0ull,r2=~0ull,r3=~0ull;
        #pragma unroll
        for (int z=0; z<4; ++z)
            #pragma unroll
            for (int s=0; s<4; ++s){
                unsigned long long c = sk[z][threadIdx.x][s];
                if (c < r3) insert4(r0,r1,r2,r3,c);
            }
        unsigned long long rr[4] = {r0,r1,r2,r3};
        #pragma unroll
        for (int r=0; r<4; ++r){
            float d  = ord2f((unsigned)(rr[r] >> 32));
            int idx  = (int)(unsigned)rr[r];
            g_knn_d[qq*4+r]  = d;
            g_knn_i[qq*4+r]  = idx;
            out[DIST_OFF + qq*4+r] = d;
        }
    }
}

// ---------------- K4: S[n,k] = sum_m 1/dist ----------------
__global__ void k_wsum(){
    int nk = blockIdx.x;
    int n = nk / KB, k = nk % KB;
    float acc = 0.f;
    for (int m = threadIdx.x; m < MB; m += 256)
        acc += 1.0f / g_knn_d[(n*MB + m)*KB + k];
    __shared__ float sb[256];
    sb[threadIdx.x] = acc;
    __syncthreads();
    for (int s=128; s>0; s>>=1){
        if (threadIdx.x < s) sb[threadIdx.x] += sb[threadIdx.x+s];
        __syncthreads();
    }
    if (threadIdx.x == 0) g_wsum[nk] = sb[0];
}

// ---------------- K5: triplane sampling (warp=query, lane=channel) ----------------
__global__ __launch_bounds__(256) void k_tex(const float* __restrict__ coords){
    int q = blockIdx.x*8 + (threadIdx.x >> 5);
    int lane = threadIdx.x & 31;
    int n = q / MB;
    float c0 = __ldg(&coords[3*q+0]);
    float c1 = __ldg(&coords[3*q+1]);
    float c2 = __ldg(&coords[3*q+2]);
    float gxs[3] = {c0, c0, c2};
    float gys[3] = {c1, c2, c0};
    float acc = 0.f;
    #pragma unroll
    for (int pl=0; pl<3; ++pl){
        float x = (gxs[pl]+1.f)*(HPX*0.5f) - 0.5f;
        float y = (gys[pl]+1.f)*(HPX*0.5f) - 0.5f;
        float fx0 = floorf(x), fy0 = floorf(y);
        int ix0 = (int)fx0, iy0 = (int)fy0;
        float wx1 = x - fx0, wx0 = 1.f - wx1;
        float wy1 = y - fy0, wy0 = 1.f - wy1;
        const float* base = g_texT + (size_t)(n*3 + pl)*REG*REG*CB;
        #pragma unroll
        for (int dy=0; dy<2; ++dy)
            #pragma unroll
            for (int dx=0; dx<2; ++dx){
                int ix = ix0 + dx, iy = iy0 + dy;
                bool v = (ix>=0) & (ix<HPX) & (iy>=0) & (iy<HPX);
                int rx = min(max(ix-ROFF,0), REG-1);
                int ry = min(max(iy-ROFF,0), REG-1);
                float w = (dx?wx1:wx0) * (dy?wy1:wy0) * (v?1.f:0.f);
                acc = fmaf(w, base[(ry*REG + rx)*CB + lane], acc);
            }
    }
    g_feat[q*64 + lane] = acc * (1.f/3.f);
}

// ---------------- K6: per-neighbor MLP + weighted sum (warp=query) ----------------
__global__ __launch_bounds__(256) void k_pmlp(const float* __restrict__ coords,
                                              const float* __restrict__ emb,
                                              const float* __restrict__ pw1, const float* __restrict__ pb1,
                                              const float* __restrict__ pw2, const float* __restrict__ pb2){
    __shared__ __align__(16) float s_w1[59*64];
    __shared__ __align__(8)  float s_b1[64];
    __shared__ __align__(16) float s_w2[64*32];
    __shared__ float s_b2[32];
    __shared__ float s_in[8][60];
    __shared__ float s_h [8][64];

    for (int i = threadIdx.x; i < 59*64; i += 256) s_w1[i] = pw1[i];
    for (int i = threadIdx.x; i < 64;    i += 256) s_b1[i] = pb1[i];
    for (int i = threadIdx.x; i < 64*32; i += 256) s_w2[i] = pw2[i];
    for (int i = threadIdx.x; i < 32;    i += 256) s_b2[i] = pb2[i];
    __syncthreads();

    int w = threadIdx.x >> 5, lane = threadIdx.x & 31;
    int q = blockIdx.x*8 + w;
    int n = q / MB;
    float cx = __ldg(&coords[3*q+0]);
    float cy = __ldg(&coords[3*q+1]);
    float cz = __ldg(&coords[3*q+2]);
    float invS[4];
    #pragma unroll
    for (int k=0;k<4;++k) invS[k] = 1.0f / g_wsum[n*KB + k];

    float pts = 0.f;
    #pragma unroll 1
    for (int k=0; k<4; ++k){
        int   idx  = g_knn_i[q*4+k];
        float dist = g_knn_d[q*4+k];
        float4 p = __ldg(&g_pts4[n*PB + idx]);
        float rx = cx - p.x, ry = cy - p.y, rz = cz - p.z;
        float L = sqrtf(rx*rx + ry*ry + rz*rz);
        L = fmaxf(L, 1e-12f);
        rx /= L; ry /= L; rz /= L;

        s_in[w][lane] = emb[idx*32 + lane];
        if (lane < 12){
            float comp = (lane<4)?rx:((lane<8)?ry:rz);
            s_in[w][32+lane] = sinf(comp * (float)(1<<(lane&3)));
        } else if (lane < 24){
            int l = lane-12;
            float comp = (l<4)?rx:((l<8)?ry:rz);
            s_in[w][32+lane] = cosf(comp * (float)(l<4 ? (1<<l) : (1<<(l&3))));
        } else if (lane < 27){
            s_in[w][32+lane] = (lane==24)?rx:((lane==25)?ry:rz);
        }
        __syncwarp();

        float a0 = s_b1[2*lane], a1 = s_b1[2*lane+1];
        #pragma unroll 4
        for (int i=0;i<59;++i){
            float ai = s_in[w][i];
            float2 wv = *(const float2*)&s_w1[i*64 + 2*lane];
            a0 = fmaf(ai, wv.x, a0);
            a1 = fmaf(ai, wv.y, a1);
        }
        s_h[w][2*lane]   = fmaxf(a0, 0.f);
        s_h[w][2*lane+1] = fmaxf(a1, 0.f);
        __syncwarp();

        float acc = s_b2[lane];
        #pragma unroll 8
        for (int i=0;i<64;++i)
            acc = fmaf(s_h[w][i], s_w2[i*32 + lane], acc);

        float wk = (1.0f/dist) * invS[k];
        pts = fmaf(acc, wk, pts);
        __syncwarp();
    }
    g_feat[q*64 + 32 + lane] = pts;
}

// ---------------- K7: generic dense layer [NQ,I] @ [I,O] + b ----------------
template<int I, int O, bool RELU>
__global__ __launch_bounds__(256) void k_dense(const float* __restrict__ A,
                                               const float* __restrict__ W,
                                               const float* __restrict__ Bv,
                                               float* __restrict__ Out){
    __shared__ float s_act[64*33];
    __shared__ __align__(16) float s_w[32*O];
    __shared__ __align__(8)  float s_b[O];
    const int t = threadIdx.x;
    for (int i=t;i<O;i+=256) s_b[i]=Bv[i];
    int qg = t >> 3;        // 0..31 -> queries qg, qg+32
    int part = t & 7;
    int qb = blockIdx.x * 64;

    float2 acc0[O/16], acc1[O/16];
    #pragma unroll
    for (int j=0;j<O/16;++j){ acc0[j]=make_float2(0.f,0.f); acc1[j]=make_float2(0.f,0.f); }

    for (int kc=0;kc<I/32;++kc){
        __syncthreads();
        for (int x=t;x<64*32;x+=256){
            int q=x>>5, ii=x&31;
            s_act[q*33+ii]=A[(qb+q)*I + kc*32+ii];
        }
        for (int x=t;x<32*O;x+=256) s_w[x]=W[kc*32*O + x];
        __syncthreads();
        #pragma unroll 4
        for (int ii=0;ii<32;++ii){
            float a0=s_act[qg*33+ii], a1=s_act[(qg+32)*33+ii];
            #pragma unroll
            for (int j=0;j<O/16;++j){
                float2 wv=*(const float2*)&s_w[ii*O + j*16 + 2*part];
                acc0[j].x = fmaf(a0,wv.x,acc0[j].x); acc0[j].y = fmaf(a0,wv.y,acc0[j].y);
                acc1[j].x = fmaf(a1,wv.x,acc1[j].x); acc1[j].y = fmaf(a1,wv.y,acc1[j].y);
            }
        }
    }
    #pragma unroll
    for (int j=0;j<O/16;++j){
        int o=j*16+2*part;
        float2 b=*(const float2*)&s_b[o];
        float2 v0=make_float2(acc0[j].x+b.x, acc0[j].y+b.y);
        float2 v1=make_float2(acc1[j].x+b.x, acc1[j].y+b.y);
        if (RELU){
            v0.x=fmaxf(v0.x,0.f); v0.y=fmaxf(v0.y,0.f);
            v1.x=fmaxf(v1.x,0.f); v1.y=fmaxf(v1.y,0.f);
        }
        *(float2*)&Out[(size_t)(qb+qg)*O+o]=v0;
        *(float2*)&Out[(size_t)(qb+qg+32)*O+o]=v1;
    }
}

// ---------------- K8: density head + rgb layer 1 ----------------
__global__ __launch_bounds__(256) void k_headA(const float* __restrict__ coords,
                                               const float* __restrict__ dirs,
                                               const float* __restrict__ dw, const float* __restrict__ db,
                                               const float* __restrict__ rw1, const float* __restrict__ rb1,
                                               float* __restrict__ out){
    __shared__ __align__(16) float s_w[155*64];
    __shared__ __align__(8)  float s_b1[64];
    __shared__ float s_in[8][156];

    for (int i=threadIdx.x;i<155*64;i+=256) s_w[i]=rw1[i];
    for (int i=threadIdx.x;i<64;i+=256) s_b1[i]=rb1[i];
    __syncthreads();

    int w = threadIdx.x >> 5, lane = threadIdx.x & 31;
    int q = blockIdx.x*8 + w;

    float4 f4 = *(const float4*)&g_h3[(size_t)q*128 + lane*4];
    s_in[w][lane*4+0]=f4.x; s_in[w][lane*4+1]=f4.y;
    s_in[w][lane*4+2]=f4.z; s_in[w][lane*4+3]=f4.w;

    float dx=__ldg(&dirs[3*q+0]), dy=__ldg(&dirs[3*q+1]), dz=__ldg(&dirs[3*q+2]);
    float L=sqrtf(dx*dx+dy*dy+dz*dz); L=fmaxf(L,1e-12f);
    dx/=L; dy/=L; dz/=L;
    if (lane < 12){
        float comp=(lane<4)?dx:((lane<8)?dy:dz);
        s_in[w][128+lane]=sinf(comp*(float)(1<<(lane&3)));
    } else if (lane < 24){
        int l=lane-12;
        float comp=(l<4)?dx:((l<8)?dy:dz);
        s_in[w][128+lane]=cosf(comp*(float)(1<<(l&3)));
    } else if (lane < 27){
        s_in[w][128+lane]=(lane==24)?dx:((lane==25)?dy:dz);
    }
    __syncwarp();

    // density
    float part=0.f;
    #pragma unroll
    for (int r=0;r<4;++r){
        int i=lane*4+r;
        part = fmaf(s_in[w][i], __ldg(&dw[i]), part);
    }
    #pragma unroll
    for (int s=16;s>0;s>>=1) part += __shfl_xor_sync(0xffffffffu, part, s);
    if (lane==0){
        float u = part + __ldg(&db[0]);
        float x = 10.f*u;
        float sp = (x > 20.f) ? x : log1pf(expf(x));
        float c0=__ldg(&coords[3*q+0]), c1=__ldg(&coords[3*q+1]), c2=__ldg(&coords[3*q+2]);
        bool sel = (c0>-1.f)&&(c0<1.f)&&(c1>-1.f)&&(c1<1.f)&&(c2>-1.f)&&(c2<1.f);
        float raw = (sp*0.1f) * (sel?1.f:0.f);
        out[DENS_OFF + q] = 1.f - expf(-raw);
    }

    float a0=s_b1[2*lane], a1=s_b1[2*lane+1];
    #pragma unroll 5
    for (int i=0;i<155;++i){
        float ai=s_in[w][i];
        float2 wv=*(const float2*)&s_w[i*64 + 2*lane];
        a0=fmaf(ai,wv.x,a0); a1=fmaf(ai,wv.y,a1);
    }
    float2 hv = make_float2(fmaxf(a0,0.f), fmaxf(a1,0.f));
    *(float2*)&g_hr[(size_t)q*64 + 2*lane] = hv;
}

// ---------------- K9: rgb layer 2 + sigmoid ----------------
__global__ __launch_bounds__(256) void k_headB(const float* __restrict__ rw2,
                                               const float* __restrict__ rb2,
                                               float* __restrict__ out){
    __shared__ __align__(16) float s_w2[64*32];
    __shared__ float s_b2[32];
    __shared__ float s_h[8][64];
    for (int i=threadIdx.x;i<64*32;i+=256) s_w2[i]=rw2[i];
    for (int i=threadIdx.x;i<32;i+=256) s_b2[i]=rb2[i];
    __syncthreads();

    int w=threadIdx.x>>5, lane=threadIdx.x&31;
    int q=blockIdx.x*8 + w;
    s_h[w][lane]    = g_hr[(size_t)q*64 + lane];
    s_h[w][32+lane] = g_hr[(size_t)q*64 + 32 + lane];
    __syncwarp();

    float acc = s_b2[lane];
    #pragma unroll 8
    for (int i=0;i<64;++i)
        acc = fmaf(s_h[w][i], s_w2[i*32+lane], acc);
    if (lane < 3)
        acc = 1.f/(1.f+expf(-acc)) * 1.002f - 0.001f;
    out[RGB_OFF + (size_t)q*32 + lane] = acc;
}

// ---------------- launcher ----------------
extern "C" void kernel_launch(void* const* d_in, const int* in_sizes, int n_in,
                              void* d_out, int out_size) {
    const float* coords = (const float*)d_in[0];
    const float* dirs   = (const float*)d_in[1];
    const float* ppos   = (const float*)d_in[2];
    const float* tpl    = (const float*)d_in[3];
    const float* emb    = (const float*)d_in[4];
    const float* pw1    = (const float*)d_in[5];
    const float* pb1    = (const float*)d_in[6];
    const float* pw2    = (const float*)d_in[7];
    const float* pb2    = (const float*)d_in[8];
    const float* fw1    = (const float*)d_in[9];
    const float* fb1    = (const float*)d_in[10];
    const float* fw2    = (const float*)d_in[11];
    const float* fb2    = (const float*)d_in[12];
    const float* fw3    = (const float*)d_in[13];
    const float* fb3    = (const float*)d_in[14];
    const float* dw     = (const float*)d_in[15];
    const float* db     = (const float*)d_in[16];
    const float* rw1    = (const float*)d_in[17];
    const float* rb1    = (const float*)d_in[18];
    const float* rw2    = (const float*)d_in[19];
    const float* rb2    = (const float*)d_in[20];
    float* out = (float*)d_out;

    float* d_h1; float* d_h2; float* d_h3; float* d_feat;
    cudaGetSymbolAddress((void**)&d_feat, g_feat);
    cudaGetSymbolAddress((void**)&d_h1, g_h1);
    cudaGetSymbolAddress((void**)&d_h2, g_h2);
    cudaGetSymbolAddress((void**)&d_h3, g_h3);

    k_prep<<<(NB*PB+255)/256, 256>>>(ppos);
    k_transpose<<<dim3(5,129,6), dim3(32,32)>>>(tpl);
    k_knn<<<NQ/32, 128>>>(coords, out);
    k_wsum<<<NB*KB, 256>>>();
    k_tex<<<NQ/8, 256>>>(coords);
    k_pmlp<<<NQ/8, 256>>>(coords, emb, pw1, pb1, pw2, pb2);
    k_dense<64,128,true><<<NQ/64, 256>>>(d_feat, fw1, fb1, d_h1);
    k_dense<128,128,true><<<NQ/64, 256>>>(d_h1, fw2, fb2, d_h2);
    k_dense<128,128,false><<<NQ/64, 256>>>(d_h2, fw3, fb3, d_h3);
    k_headA<<<NQ/8, 256>>>(coords, dirs, dw, db, rw1, rb1, out);
    k_headB<<<NQ/8, 256>>>(rw2, rb2, out);
}